// round 9
// baseline (speedup 1.0000x reference)
#include <cuda_runtime.h>
#include <cstdint>

#define B 8
#define H 12
#define S 4096
#define D 64
#define BH (B*H)        // 96
#define TOPK 128

// Scratch (device globals; no allocation allowed)
__device__ int      g_idx[BH * TOPK];     // selected indices per head
__device__ unsigned g_selmask[BH * 128];  // 4096-bit selected-row bitmap per head

__device__ __forceinline__ unsigned key_of(float f) {
    unsigned u = __float_as_uint(f);
    return (u & 0x80000000u) ? ~u : (u | 0x80000000u);
}

__device__ __forceinline__ float to_tf32(float x) {
    unsigned u;
    asm("cvt.rna.tf32.f32 %0, %1;" : "=r"(u) : "f"(x));
    return __uint_as_float(u);
}

__device__ __forceinline__ void mma_tf32(float c[4],
                                         unsigned a0, unsigned a1, unsigned a2, unsigned a3,
                                         unsigned b0, unsigned b1) {
    asm volatile(
        "mma.sync.aligned.m16n8k8.row.col.f32.tf32.tf32.f32 "
        "{%0,%1,%2,%3}, {%4,%5,%6,%7}, {%8,%9}, {%0,%1,%2,%3};"
        : "+f"(c[0]), "+f"(c[1]), "+f"(c[2]), "+f"(c[3])
        : "r"(a0), "r"(a1), "r"(a2), "r"(a3), "r"(b0), "r"(b1));
}

// ---------------------------------------------------------------------------
// Kernel 1 (FUSED): importance (mean + std, ddof=1) + exact top-128 radix
// select. One CTA per head, 512 threads. Keys never leave shared memory.
// ---------------------------------------------------------------------------
__global__ __launch_bounds__(512)
void select_kernel(const float* __restrict__ q) {
    __shared__ unsigned keys[S];       // 16 KB
    __shared__ int hist[256];
    __shared__ unsigned mask[128];
    __shared__ int s_digit, s_need, s_n;

    const int bh  = blockIdx.x;
    const int tid = threadIdx.x;
    const int lane = tid & 31;
    const int w    = tid >> 5;         // 16 warps
    const int sub  = lane >> 3;        // 0..3
    const int cl   = lane & 7;         // 8 lanes per row

    const float* qh = q + (size_t)bh * S * D;

    // ---- Phase 1: importance keys into smem.
    // Per iteration: warp covers 16 rows (4 per lane-group), 8 LDG.128/thread.
    // 16 warps x 16 rows = 256 rows/iter; 16 iterations for S=4096.
    #pragma unroll 1
    for (int iter = 0; iter < 16; iter++) {
        int r0 = iter * 256 + w * 16 + sub;    // rows r0, r0+4, r0+8, r0+12

        float4 a[4], b[4];
        #pragma unroll
        for (int t = 0; t < 4; t++) {
            const float4* p = reinterpret_cast<const float4*>(qh + (size_t)(r0 + 4 * t) * D) + cl;
            a[t] = p[0];
            b[t] = p[8];
        }

        float s[4], s2[4];
        #pragma unroll
        for (int t = 0; t < 4; t++) {
            s[t]  = (a[t].x + a[t].y) + (a[t].z + a[t].w) +
                    (b[t].x + b[t].y) + (b[t].z + b[t].w);
            s2[t] = a[t].x * a[t].x + a[t].y * a[t].y + a[t].z * a[t].z + a[t].w * a[t].w +
                    b[t].x * b[t].x + b[t].y * b[t].y + b[t].z * b[t].z + b[t].w * b[t].w;
        }
        #pragma unroll
        for (int o = 1; o < 8; o <<= 1)
            #pragma unroll
            for (int t = 0; t < 4; t++) {
                s[t]  += __shfl_xor_sync(0xFFFFFFFFu, s[t],  o);
                s2[t] += __shfl_xor_sync(0xFFFFFFFFu, s2[t], o);
            }

        if (cl == 0) {
            #pragma unroll
            for (int t = 0; t < 4; t++) {
                float mean = s[t] * (1.0f / 64.0f);
                float var  = (s2[t] - s[t] * mean) * (1.0f / 63.0f);
                keys[r0 + 4 * t] = key_of(mean + sqrtf(fmaxf(var, 0.0f)));
            }
        }
    }
    if (tid < 128) mask[tid] = 0u;
    __syncthreads();

    // ---- Phase 2: 4-pass MSB radix select for the 128th-largest key.
    unsigned prefix = 0u;
    int need = TOPK;

    #pragma unroll
    for (int shift = 24; shift >= 0; shift -= 8) {
        if (tid < 256) hist[tid] = 0;
        __syncthreads();

        unsigned pmask = (shift == 24) ? 0u : (0xFFFFFFFFu << (shift + 8));
        for (int i = tid; i < S; i += 512) {
            unsigned u = keys[i];
            if ((u & pmask) == prefix)
                atomicAdd(&hist[(u >> shift) & 255u], 1);
        }
        __syncthreads();

        if (tid < 32) {
            int base = 255 - tid * 8;
            int h[8];
            int gs = 0;
            #pragma unroll
            for (int j = 0; j < 8; j++) { h[j] = hist[base - j]; gs += h[j]; }
            int pre = gs;
            #pragma unroll
            for (int o = 1; o < 32; o <<= 1) {
                int t = __shfl_up_sync(0xFFFFFFFFu, pre, o);
                if (tid >= o) pre += t;
            }
            int excl = pre - gs;
            if (excl < need && need <= pre) {
                int cum = excl, j = 0;
                #pragma unroll
                for (; j < 8; j++) { cum += h[j]; if (cum >= need) break; }
                s_digit = base - j;
                s_need  = need - (cum - h[j]);
            }
        }
        __syncthreads();
        prefix |= ((unsigned)s_digit) << shift;
        need = s_need;
        __syncthreads();
    }

    const unsigned T = prefix;

    // ---- Phase 3: collect indices + bitmap.
    if (tid == 0) s_n = 0;
    __syncthreads();
    for (int i = tid; i < S; i += 512) {
        if (keys[i] > T) {
            int p = atomicAdd(&s_n, 1);
            g_idx[bh * TOPK + p] = i;
        }
    }
    __syncthreads();
    for (int i = tid; i < S; i += 512) {
        if (keys[i] == T) {
            int p = atomicAdd(&s_n, 1);
            if (p < TOPK) g_idx[bh * TOPK + p] = i;
        }
    }
    __syncthreads();
    if (tid < TOPK) {
        int i = g_idx[bh * TOPK + tid];
        atomicOr(&mask[i >> 5], 1u << (i & 31));
    }
    __syncthreads();
    if (tid < 128) g_selmask[bh * 128 + tid] = mask[tid];
}

// ---------------------------------------------------------------------------
// Kernel 2: zero all UNSELECTED output rows (97 MB); overlaps attn.
// ---------------------------------------------------------------------------
__global__ __launch_bounds__(256)
void zero_kernel(float* __restrict__ out) {
    __shared__ unsigned mask[32];
    const int bh   = blockIdx.x >> 2;
    const int quad = blockIdx.x & 3;
    const int tid  = threadIdx.x;
    if (tid < 32) mask[tid] = g_selmask[bh * 128 + quad * 32 + tid];
    __syncthreads();

    float4* obase = reinterpret_cast<float4*>(out + (size_t)bh * S * D) + (quad * 1024) * 16;
    const float4 z = make_float4(0.f, 0.f, 0.f, 0.f);

    for (int i = tid; i < 1024 * 16; i += 256) {
        int r = i >> 4;
        if (!(mask[r >> 5] & (1u << (r & 31))))
            obase[i] = z;
    }
}

// ---------------------------------------------------------------------------
// Kernel 3: gathered attention, tf32 mma.sync. ONE CTA per head:
// 96 CTAs x 512 threads (16 warps), 128 q-rows. Single wave.
// ---------------------------------------------------------------------------
#define PITCH  68
#define PPITCH 132

__global__ __launch_bounds__(512, 1)
void attn_kernel(const float* __restrict__ q, const float* __restrict__ k,
                 const float* __restrict__ v, float* __restrict__ out) {
    extern __shared__ float sm[];
    float* qs = sm;                          // 128 x PITCH (dead after GEMM1)
    float* ks = qs + 128 * PITCH;            // 128 x PITCH (dead after GEMM1)
    float* vs = ks + 128 * PITCH;            // 128 x PITCH
    float* ps = sm;                          // 128 x PPITCH alias over qs+ks
    __shared__ int sidx[TOPK];

    const int bh  = blockIdx.x;
    const int tid = threadIdx.x;
    if (tid < TOPK) sidx[tid] = g_idx[bh * TOPK + tid];
    __syncthreads();

    const size_t base = (size_t)bh * S * D;

    // Gather q,k,v: 4 threads per row, 4 float4 each; tf32-round on the fly.
    {
        int r = tid >> 2, p = tid & 3;
        size_t goff = base + (size_t)sidx[r] * D + p * 16;
        const float4* gq = reinterpret_cast<const float4*>(q + goff);
        const float4* gk = reinterpret_cast<const float4*>(k + goff);
        const float4* gv = reinterpret_cast<const float4*>(v + goff);
        float* dq = qs + r * PITCH + p * 16;
        float* dk = ks + r * PITCH + p * 16;
        float* dv = vs + r * PITCH + p * 16;
        #pragma unroll
        for (int i = 0; i < 4; i++) {
            float4 q4 = gq[i], k4 = gk[i], v4 = gv[i];
            q4.x = to_tf32(q4.x); q4.y = to_tf32(q4.y);
            q4.z = to_tf32(q4.z); q4.w = to_tf32(q4.w);
            k4.x = to_tf32(k4.x); k4.y = to_tf32(k4.y);
            k4.z = to_tf32(k4.z); k4.w = to_tf32(k4.w);
            v4.x = to_tf32(v4.x); v4.y = to_tf32(v4.y);
            v4.z = to_tf32(v4.z); v4.w = to_tf32(v4.w);
            reinterpret_cast<float4*>(dq)[i] = q4;
            reinterpret_cast<float4*>(dk)[i] = k4;
            reinterpret_cast<float4*>(dv)[i] = v4;
        }
    }
    __syncthreads();

    const int lane = tid & 31;
    const int w    = tid >> 5;           // 16 warps
    const int wm   = w & 3;
    const int wn   = w >> 2;
    const int m0   = wm * 32;
    const int lr   = lane >> 2;
    const int lc   = lane & 3;

    // GEMM1: warp tile 32x32; 8 k-steps
    float c1[2][4][4];
    #pragma unroll
    for (int mi = 0; mi < 2; mi++)
        #pragma unroll
        for (int nb = 0; nb < 4; nb++)
            #pragma unroll
            for (int j = 0; j < 4; j++) c1[mi][nb][j] = 0.0f;

    #pragma unroll
    for (int kk = 0; kk < 8; kk++) {
        const int k0 = kk * 8;
        unsigned a[2][4];
        #pragma unroll
        for (int mi = 0; mi < 2; mi++) {
            const int mr = m0 + mi * 16;
            a[mi][0] = __float_as_uint(qs[(mr + lr)     * PITCH + k0 + lc]);
            a[mi][1] = __float_as_uint(qs[(mr + lr + 8) * PITCH + k0 + lc]);
            a[mi][2] = __float_as_uint(qs[(mr + lr)     * PITCH + k0 + lc + 4]);
            a[mi][3] = __float_as_uint(qs[(mr + lr + 8) * PITCH + k0 + lc + 4]);
        }
        #pragma unroll
        for (int nb = 0; nb < 4; nb++) {
            const int n0 = wn * 32 + nb * 8;
            unsigned b0 = __float_as_uint(ks[(n0 + lr) * PITCH + k0 + lc]);
            unsigned b1 = __float_as_uint(ks[(n0 + lr) * PITCH + k0 + lc + 4]);
            #pragma unroll
            for (int mi = 0; mi < 2; mi++)
                mma_tf32(c1[mi][nb], a[mi][0], a[mi][1], a[mi][2], a[mi][3], b0, b1);
        }
    }
    __syncthreads();

    #pragma unroll
    for (int mi = 0; mi < 2; mi++)
        #pragma unroll
        for (int nb = 0; nb < 4; nb++) {
            const int mr  = m0 + mi * 16;
            const int col = wn * 32 + nb * 8 + lc * 2;
            ps[(mr + lr)     * PPITCH + col]     = c1[mi][nb][0] * 0.125f;
            ps[(mr + lr)     * PPITCH + col + 1] = c1[mi][nb][1] * 0.125f;
            ps[(mr + lr + 8) * PPITCH + col]     = c1[mi][nb][2] * 0.125f;
            ps[(mr + lr + 8) * PPITCH + col + 1] = c1[mi][nb][3] * 0.125f;
        }
    __syncthreads();

    // Row softmax: 16 warps x 8 rows, tf32-rounded probs
    #pragma unroll
    for (int rr = 0; rr < 8; rr++) {
        int r = w * 8 + rr;
        float* row = ps + r * PPITCH;
        float x[4];
        float mx = -1e30f;
        #pragma unroll
        for (int c = 0; c < 4; c++) { x[c] = row[lane + 32 * c]; mx = fmaxf(mx, x[c]); }
        #pragma unroll
        for (int o = 16; o; o >>= 1) mx = fmaxf(mx, __shfl_xor_sync(0xFFFFFFFFu, mx, o));
        float ssum = 0.0f;
        #pragma unroll
        for (int c = 0; c < 4; c++) { x[c] = __expf(x[c] - mx); ssum += x[c]; }
        #pragma unroll
        for (int o = 16; o; o >>= 1) ssum += __shfl_xor_sync(0xFFFFFFFFu, ssum, o);
        float inv = 1.0f / ssum;
        #pragma unroll
        for (int c = 0; c < 4; c++) row[lane + 32 * c] = to_tf32(x[c] * inv);
    }
    __syncthreads();

    // GEMM2: warp tile 32x16 of O[128x64]; 16 k-steps
    float c2[2][2][4];
    #pragma unroll
    for (int mi = 0; mi < 2; mi++)
        #pragma unroll
        for (int nb = 0; nb < 2; nb++)
            #pragma unroll
            for (int j = 0; j < 4; j++) c2[mi][nb][j] = 0.0f;

    #pragma unroll
    for (int kk = 0; kk < 16; kk++) {
        const int k0 = kk * 8;
        unsigned a[2][4];
        #pragma unroll
        for (int mi = 0; mi < 2; mi++) {
            const int mr = m0 + mi * 16;
            a[mi][0] = __float_as_uint(ps[(mr + lr)     * PPITCH + k0 + lc]);
            a[mi][1] = __float_as_uint(ps[(mr + lr + 8) * PPITCH + k0 + lc]);
            a[mi][2] = __float_as_uint(ps[(mr + lr)     * PPITCH + k0 + lc + 4]);
            a[mi][3] = __float_as_uint(ps[(mr + lr + 8) * PPITCH + k0 + lc + 4]);
        }
        #pragma unroll
        for (int nb = 0; nb < 2; nb++) {
            const int n0 = wn * 16 + nb * 8;
            unsigned b0 = __float_as_uint(vs[(k0 + lc)     * PITCH + n0 + lr]);
            unsigned b1 = __float_as_uint(vs[(k0 + lc + 4) * PITCH + n0 + lr]);
            #pragma unroll
            for (int mi = 0; mi < 2; mi++)
                mma_tf32(c2[mi][nb], a[mi][0], a[mi][1], a[mi][2], a[mi][3], b0, b1);
        }
    }

    // Epilogue: scatter warp tile to selected output rows
    #pragma unroll
    for (int mi = 0; mi < 2; mi++) {
        int r0g = sidx[m0 + mi * 16 + lr];
        int r1g = sidx[m0 + mi * 16 + lr + 8];
        float* o0 = out + (size_t)bh * S * D + (size_t)r0g * D;
        float* o1 = out + (size_t)bh * S * D + (size_t)r1g * D;
        #pragma unroll
        for (int nb = 0; nb < 2; nb++) {
            const int d0 = wn * 16 + nb * 8 + lc * 2;
            *reinterpret_cast<float2*>(o0 + d0) = make_float2(c2[mi][nb][0], c2[mi][nb][1]);
            *reinterpret_cast<float2*>(o1 + d0) = make_float2(c2[mi][nb][2], c2[mi][nb][3]);
        }
    }
}

// ---------------------------------------------------------------------------
extern "C" void kernel_launch(void* const* d_in, const int* in_sizes, int n_in,
                              void* d_out, int out_size) {
    const float* q = (const float*)d_in[0];
    const float* k = (const float*)d_in[1];
    const float* v = (const float*)d_in[2];
    float* out = (float*)d_out;

    static cudaStream_t s1 = nullptr;
    static cudaEvent_t  e0 = nullptr, e1 = nullptr;
    if (s1 == nullptr) {
        cudaStreamCreateWithFlags(&s1, cudaStreamNonBlocking);
        cudaEventCreateWithFlags(&e0, cudaEventDisableTiming);
        cudaEventCreateWithFlags(&e1, cudaEventDisableTiming);
    }

    const int attn_smem = (3 * 128 * PITCH) * (int)sizeof(float);
    cudaFuncSetAttribute(attn_kernel, cudaFuncAttributeMaxDynamicSharedMemorySize,
                         attn_smem);

    // 1) fused importance + exact top-128 + bitmap (one CTA per head)
    select_kernel<<<BH, 512>>>(q);

    // Fork: zero unselected output rows on side stream while attn
    // computes+writes selected rows on the main stream (disjoint rows).
    cudaEventRecord(e0, 0);
    cudaStreamWaitEvent(s1, e0, 0);
    zero_kernel<<<BH * 4, 256, 0, s1>>>(out);
    cudaEventRecord(e1, s1);

    // 2) tf32 tensor-core gathered attention (1 CTA per head, single wave)
    attn_kernel<<<BH, 512, attn_smem>>>(q, k, v, out);

    // Join
    cudaStreamWaitEvent(0, e1, 0);
}

// round 10
// speedup vs baseline: 1.1134x; 1.1134x over previous
#include <cuda_runtime.h>
#include <cstdint>

#define B 8
#define H 12
#define S 4096
#define D 64
#define BH (B*H)        // 96
#define TOPK 128

// Scratch (device globals; no allocation allowed)
__device__ unsigned g_key[BH * S];   // order-preserving uint importance keys

__device__ __forceinline__ unsigned key_of(float f) {
    unsigned u = __float_as_uint(f);
    return (u & 0x80000000u) ? ~u : (u | 0x80000000u);
}

__device__ __forceinline__ float to_tf32(float x) {
    unsigned u;
    asm("cvt.rna.tf32.f32 %0, %1;" : "=r"(u) : "f"(x));
    return __uint_as_float(u);
}

__device__ __forceinline__ void mma_tf32(float c[4],
                                         unsigned a0, unsigned a1, unsigned a2, unsigned a3,
                                         unsigned b0, unsigned b1) {
    asm volatile(
        "mma.sync.aligned.m16n8k8.row.col.f32.tf32.tf32.f32 "
        "{%0,%1,%2,%3}, {%4,%5,%6,%7}, {%8,%9}, {%0,%1,%2,%3};"
        : "+f"(c[0]), "+f"(c[1]), "+f"(c[2]), "+f"(c[3])
        : "r"(a0), "r"(a1), "r"(a2), "r"(a3), "r"(b0), "r"(b1));
}

// ---------------------------------------------------------------------------
// Kernel 1: importance = mean + std(ddof=1) over D=64 -> monotone uint keys.
// Wide grid (3072 CTAs) for full HBM read bandwidth.
// ---------------------------------------------------------------------------
__global__ __launch_bounds__(256)
void imp_kernel(const float* __restrict__ q) {
    int warp = (blockIdx.x * blockDim.x + threadIdx.x) >> 5;
    int lane = threadIdx.x & 31;
    int sub  = lane >> 3;
    int cl   = lane & 7;
    int r0   = warp * 16 + sub;

    float4 a[4], b[4];
    #pragma unroll
    for (int t = 0; t < 4; t++) {
        const float4* p = reinterpret_cast<const float4*>(q + (size_t)(r0 + 4 * t) * D) + cl;
        a[t] = p[0];
        b[t] = p[8];
    }

    float s[4], s2[4];
    #pragma unroll
    for (int t = 0; t < 4; t++) {
        s[t]  = (a[t].x + a[t].y) + (a[t].z + a[t].w) +
                (b[t].x + b[t].y) + (b[t].z + b[t].w);
        s2[t] = a[t].x * a[t].x + a[t].y * a[t].y + a[t].z * a[t].z + a[t].w * a[t].w +
                b[t].x * b[t].x + b[t].y * b[t].y + b[t].z * b[t].z + b[t].w * b[t].w;
    }
    #pragma unroll
    for (int o = 1; o < 8; o <<= 1)
        #pragma unroll
        for (int t = 0; t < 4; t++) {
            s[t]  += __shfl_xor_sync(0xFFFFFFFFu, s[t],  o);
            s2[t] += __shfl_xor_sync(0xFFFFFFFFu, s2[t], o);
        }

    if (cl == 0) {
        #pragma unroll
        for (int t = 0; t < 4; t++) {
            float mean = s[t] * (1.0f / 64.0f);
            float var  = (s2[t] - s[t] * mean) * (1.0f / 63.0f);
            g_key[r0 + 4 * t] = key_of(mean + sqrtf(fmaxf(var, 0.0f)));
        }
    }
}

// ---------------------------------------------------------------------------
// Kernel 2 (FUSED): per-head top-128 radix select + output zeroing (overlapped,
// fire-and-forget stores) + tf32 tensor-core attention + scatter.
// One CTA per head: 96 CTAs x 512 threads, single wave.
// Dynamic smem: keys[4096] aliases the same region later used for qs/ks/vs.
// ---------------------------------------------------------------------------
#define PITCH  68
#define PPITCH 132

__global__ __launch_bounds__(512, 1)
void fused_kernel(const float* __restrict__ q, const float* __restrict__ k,
                  const float* __restrict__ v, float* __restrict__ out) {
    extern __shared__ float sm[];
    unsigned* keys = reinterpret_cast<unsigned*>(sm);   // 16 KB, dead after select
    float* qs = sm;                          // 128 x PITCH (dead after GEMM1)
    float* ks = qs + 128 * PITCH;            // 128 x PITCH (dead after GEMM1)
    float* vs = ks + 128 * PITCH;            // 128 x PITCH
    float* ps = sm;                          // 128 x PPITCH alias over qs+ks

    __shared__ int      sidx[TOPK];
    __shared__ unsigned mask[128];
    __shared__ int      hist[256];
    __shared__ int      s_digit, s_need, s_n;

    const int bh  = blockIdx.x;
    const int tid = threadIdx.x;
    const int lane = tid & 31;
    const int w    = tid >> 5;           // 16 warps

    // ---- Phase A: load keys, radix-select the 128th largest -------------
    const unsigned* krow = g_key + (size_t)bh * S;
    for (int i = tid; i < S; i += 512) keys[i] = krow[i];
    if (tid < 128) mask[tid] = 0u;

    unsigned prefix = 0u;
    int need = TOPK;

    #pragma unroll
    for (int shift = 24; shift >= 0; shift -= 8) {
        if (tid < 256) hist[tid] = 0;
        __syncthreads();

        unsigned pmask = (shift == 24) ? 0u : (0xFFFFFFFFu << (shift + 8));
        for (int i = tid; i < S; i += 512) {
            unsigned u = keys[i];
            if ((u & pmask) == prefix)
                atomicAdd(&hist[(u >> shift) & 255u], 1);
        }
        __syncthreads();

        if (tid < 32) {
            int base = 255 - tid * 8;
            int h[8];
            int gs = 0;
            #pragma unroll
            for (int j = 0; j < 8; j++) { h[j] = hist[base - j]; gs += h[j]; }
            int pre = gs;
            #pragma unroll
            for (int o = 1; o < 32; o <<= 1) {
                int t = __shfl_up_sync(0xFFFFFFFFu, pre, o);
                if (tid >= o) pre += t;
            }
            int excl = pre - gs;
            if (excl < need && need <= pre) {
                int cum = excl, j = 0;
                #pragma unroll
                for (; j < 8; j++) { cum += h[j]; if (cum >= need) break; }
                s_digit = base - j;
                s_need  = need - (cum - h[j]);
            }
        }
        __syncthreads();
        prefix |= ((unsigned)s_digit) << shift;
        need = s_need;
        __syncthreads();
    }

    const unsigned T = prefix;

    if (tid == 0) s_n = 0;
    __syncthreads();
    for (int i = tid; i < S; i += 512) {
        if (keys[i] > T) {
            int p = atomicAdd(&s_n, 1);
            sidx[p] = i;
        }
    }
    __syncthreads();
    for (int i = tid; i < S; i += 512) {
        if (keys[i] == T) {
            int p = atomicAdd(&s_n, 1);
            if (p < TOPK) sidx[p] = i;
        }
    }
    __syncthreads();
    if (tid < TOPK)
        atomicOr(&mask[sidx[tid] >> 5], 1u << (sidx[tid] & 31));
    __syncthreads();   // mask complete; keys no longer needed

    const size_t base = (size_t)bh * S * D;

    // ---- Phase B: zero unselected output rows (fire-and-forget stores).
    // These drain on the DRAM-write path while phases C-F run on LSU/tensor.
    {
        float4* obase = reinterpret_cast<float4*>(out + base);
        const float4 z = make_float4(0.f, 0.f, 0.f, 0.f);
        for (int i = tid; i < S * (D / 4); i += 512) {
            int r = i >> 4;
            if (!(mask[r >> 5] & (1u << (r & 31))))
                obase[i] = z;
        }
    }

    // ---- Phase C: gather q,k,v (tf32-rounded) into smem ------------------
    {
        int r = tid >> 2, p = tid & 3;
        size_t goff = base + (size_t)sidx[r] * D + p * 16;
        const float4* gq = reinterpret_cast<const float4*>(q + goff);
        const float4* gk = reinterpret_cast<const float4*>(k + goff);
        const float4* gv = reinterpret_cast<const float4*>(v + goff);
        float* dq = qs + r * PITCH + p * 16;
        float* dk = ks + r * PITCH + p * 16;
        float* dv = vs + r * PITCH + p * 16;
        #pragma unroll
        for (int i = 0; i < 4; i++) {
            float4 q4 = gq[i], k4 = gk[i], v4 = gv[i];
            q4.x = to_tf32(q4.x); q4.y = to_tf32(q4.y);
            q4.z = to_tf32(q4.z); q4.w = to_tf32(q4.w);
            k4.x = to_tf32(k4.x); k4.y = to_tf32(k4.y);
            k4.z = to_tf32(k4.z); k4.w = to_tf32(k4.w);
            v4.x = to_tf32(v4.x); v4.y = to_tf32(v4.y);
            v4.z = to_tf32(v4.z); v4.w = to_tf32(v4.w);
            reinterpret_cast<float4*>(dq)[i] = q4;
            reinterpret_cast<float4*>(dk)[i] = k4;
            reinterpret_cast<float4*>(dv)[i] = v4;
        }
    }
    __syncthreads();

    const int wm = w & 3;
    const int wn = w >> 2;
    const int m0 = wm * 32;
    const int lr = lane >> 2;
    const int lc = lane & 3;

    // ---- Phase D: GEMM1 (warp tile 32x32, 8 k-steps) ---------------------
    float c1[2][4][4];
    #pragma unroll
    for (int mi = 0; mi < 2; mi++)
        #pragma unroll
        for (int nb = 0; nb < 4; nb++)
            #pragma unroll
            for (int j = 0; j < 4; j++) c1[mi][nb][j] = 0.0f;

    #pragma unroll
    for (int kk = 0; kk < 8; kk++) {
        const int k0 = kk * 8;
        unsigned a[2][4];
        #pragma unroll
        for (int mi = 0; mi < 2; mi++) {
            const int mr = m0 + mi * 16;
            a[mi][0] = __float_as_uint(qs[(mr + lr)     * PITCH + k0 + lc]);
            a[mi][1] = __float_as_uint(qs[(mr + lr + 8) * PITCH + k0 + lc]);
            a[mi][2] = __float_as_uint(qs[(mr + lr)     * PITCH + k0 + lc + 4]);
            a[mi][3] = __float_as_uint(qs[(mr + lr + 8) * PITCH + k0 + lc + 4]);
        }
        #pragma unroll
        for (int nb = 0; nb < 4; nb++) {
            const int n0 = wn * 32 + nb * 8;
            unsigned b0 = __float_as_uint(ks[(n0 + lr) * PITCH + k0 + lc]);
            unsigned b1 = __float_as_uint(ks[(n0 + lr) * PITCH + k0 + lc + 4]);
            #pragma unroll
            for (int mi = 0; mi < 2; mi++)
                mma_tf32(c1[mi][nb], a[mi][0], a[mi][1], a[mi][2], a[mi][3], b0, b1);
        }
    }
    __syncthreads();   // all warps done reading qs/ks before ps overwrite

    #pragma unroll
    for (int mi = 0; mi < 2; mi++)
        #pragma unroll
        for (int nb = 0; nb < 4; nb++) {
            const int mr  = m0 + mi * 16;
            const int col = wn * 32 + nb * 8 + lc * 2;
            ps[(mr + lr)     * PPITCH + col]     = c1[mi][nb][0] * 0.125f;
            ps[(mr + lr)     * PPITCH + col + 1] = c1[mi][nb][1] * 0.125f;
            ps[(mr + lr + 8) * PPITCH + col]     = c1[mi][nb][2] * 0.125f;
            ps[(mr + lr + 8) * PPITCH + col + 1] = c1[mi][nb][3] * 0.125f;
        }
    __syncthreads();

    // ---- Phase E: row softmax (16 warps x 8 rows), tf32 probs ------------
    #pragma unroll
    for (int rr = 0; rr < 8; rr++) {
        int r = w * 8 + rr;
        float* row = ps + r * PPITCH;
        float x[4];
        float mx = -1e30f;
        #pragma unroll
        for (int c = 0; c < 4; c++) { x[c] = row[lane + 32 * c]; mx = fmaxf(mx, x[c]); }
        #pragma unroll
        for (int o = 16; o; o >>= 1) mx = fmaxf(mx, __shfl_xor_sync(0xFFFFFFFFu, mx, o));
        float ssum = 0.0f;
        #pragma unroll
        for (int c = 0; c < 4; c++) { x[c] = __expf(x[c] - mx); ssum += x[c]; }
        #pragma unroll
        for (int o = 16; o; o >>= 1) ssum += __shfl_xor_sync(0xFFFFFFFFu, ssum, o);
        float inv = 1.0f / ssum;
        #pragma unroll
        for (int c = 0; c < 4; c++) row[lane + 32 * c] = to_tf32(x[c] * inv);
    }
    __syncthreads();

    // ---- Phase F: GEMM2 (warp tile 32x16, 16 k-steps) + scatter ----------
    float c2[2][2][4];
    #pragma unroll
    for (int mi = 0; mi < 2; mi++)
        #pragma unroll
        for (int nb = 0; nb < 2; nb++)
            #pragma unroll
            for (int j = 0; j < 4; j++) c2[mi][nb][j] = 0.0f;

    #pragma unroll
    for (int kk = 0; kk < 16; kk++) {
        const int k0 = kk * 8;
        unsigned a[2][4];
        #pragma unroll
        for (int mi = 0; mi < 2; mi++) {
            const int mr = m0 + mi * 16;
            a[mi][0] = __float_as_uint(ps[(mr + lr)     * PPITCH + k0 + lc]);
            a[mi][1] = __float_as_uint(ps[(mr + lr + 8) * PPITCH + k0 + lc]);
            a[mi][2] = __float_as_uint(ps[(mr + lr)     * PPITCH + k0 + lc + 4]);
            a[mi][3] = __float_as_uint(ps[(mr + lr + 8) * PPITCH + k0 + lc + 4]);
        }
        #pragma unroll
        for (int nb = 0; nb < 2; nb++) {
            const int n0 = wn * 16 + nb * 8;
            unsigned b0 = __float_as_uint(vs[(k0 + lc)     * PITCH + n0 + lr]);
            unsigned b1 = __float_as_uint(vs[(k0 + lc + 4) * PITCH + n0 + lr]);
            #pragma unroll
            for (int mi = 0; mi < 2; mi++)
                mma_tf32(c2[mi][nb], a[mi][0], a[mi][1], a[mi][2], a[mi][3], b0, b1);
        }
    }

    #pragma unroll
    for (int mi = 0; mi < 2; mi++) {
        int r0g = sidx[m0 + mi * 16 + lr];
        int r1g = sidx[m0 + mi * 16 + lr + 8];
        float* o0 = out + base + (size_t)r0g * D;
        float* o1 = out + base + (size_t)r1g * D;
        #pragma unroll
        for (int nb = 0; nb < 2; nb++) {
            const int d0 = wn * 16 + nb * 8 + lc * 2;
            *reinterpret_cast<float2*>(o0 + d0) = make_float2(c2[mi][nb][0], c2[mi][nb][1]);
            *reinterpret_cast<float2*>(o1 + d0) = make_float2(c2[mi][nb][2], c2[mi][nb][3]);
        }
    }
}

// ---------------------------------------------------------------------------
extern "C" void kernel_launch(void* const* d_in, const int* in_sizes, int n_in,
                              void* d_out, int out_size) {
    const float* q = (const float*)d_in[0];
    const float* k = (const float*)d_in[1];
    const float* v = (const float*)d_in[2];
    float* out = (float*)d_out;

    const int fused_smem = (3 * 128 * PITCH) * (int)sizeof(float);
    cudaFuncSetAttribute(fused_kernel, cudaFuncAttributeMaxDynamicSharedMemorySize,
                         fused_smem);

    // 1) importance keys (wide grid, full HBM bandwidth)
    imp_kernel<<<(BH * S) / 128, 256>>>(q);

    // 2) fused select + zero + tensor-core attention (1 CTA per head)
    fused_kernel<<<BH, 512, fused_smem>>>(q, k, v, out);
}

// round 11
// speedup vs baseline: 1.1888x; 1.0677x over previous
#include <cuda_runtime.h>
#include <cstdint>

#define B 8
#define H 12
#define S 4096
#define D 64
#define BH (B*H)        // 96
#define TOPK 128

// Scratch (device globals; no allocation allowed)
__device__ unsigned g_key[BH * S];        // order-preserving uint importance keys
__device__ unsigned g_selmask[BH * 128];  // selected-row bitmap per head

__device__ __forceinline__ unsigned key_of(float f) {
    unsigned u = __float_as_uint(f);
    return (u & 0x80000000u) ? ~u : (u | 0x80000000u);
}

__device__ __forceinline__ float to_tf32(float x) {
    unsigned u;
    asm("cvt.rna.tf32.f32 %0, %1;" : "=r"(u) : "f"(x));
    return __uint_as_float(u);
}

__device__ __forceinline__ void mma_tf32(float c[4],
                                         unsigned a0, unsigned a1, unsigned a2, unsigned a3,
                                         unsigned b0, unsigned b1) {
    asm volatile(
        "mma.sync.aligned.m16n8k8.row.col.f32.tf32.tf32.f32 "
        "{%0,%1,%2,%3}, {%4,%5,%6,%7}, {%8,%9}, {%0,%1,%2,%3};"
        : "+f"(c[0]), "+f"(c[1]), "+f"(c[2]), "+f"(c[3])
        : "r"(a0), "r"(a1), "r"(a2), "r"(a3), "r"(b0), "r"(b1));
}

// ---------------------------------------------------------------------------
// Kernel 1: importance keys (wide grid, full HBM read bandwidth).
// ---------------------------------------------------------------------------
__global__ __launch_bounds__(256)
void imp_kernel(const float* __restrict__ q) {
    int warp = (blockIdx.x * blockDim.x + threadIdx.x) >> 5;
    int lane = threadIdx.x & 31;
    int sub  = lane >> 3;
    int cl   = lane & 7;
    int r0   = warp * 16 + sub;

    float4 a[4], b[4];
    #pragma unroll
    for (int t = 0; t < 4; t++) {
        const float4* p = reinterpret_cast<const float4*>(q + (size_t)(r0 + 4 * t) * D) + cl;
        a[t] = p[0];
        b[t] = p[8];
    }

    float s[4], s2[4];
    #pragma unroll
    for (int t = 0; t < 4; t++) {
        s[t]  = (a[t].x + a[t].y) + (a[t].z + a[t].w) +
                (b[t].x + b[t].y) + (b[t].z + b[t].w);
        s2[t] = a[t].x * a[t].x + a[t].y * a[t].y + a[t].z * a[t].z + a[t].w * a[t].w +
                b[t].x * b[t].x + b[t].y * b[t].y + b[t].z * b[t].z + b[t].w * b[t].w;
    }
    #pragma unroll
    for (int o = 1; o < 8; o <<= 1)
        #pragma unroll
        for (int t = 0; t < 4; t++) {
            s[t]  += __shfl_xor_sync(0xFFFFFFFFu, s[t],  o);
            s2[t] += __shfl_xor_sync(0xFFFFFFFFu, s2[t], o);
        }

    if (cl == 0) {
        #pragma unroll
        for (int t = 0; t < 4; t++) {
            float mean = s[t] * (1.0f / 64.0f);
            float var  = (s2[t] - s[t] * mean) * (1.0f / 63.0f);
            g_key[r0 + 4 * t] = key_of(mean + sqrtf(fmaxf(var, 0.0f)));
        }
    }
}

// ---------------------------------------------------------------------------
// Kernel 2 (FUSED): top-128 radix select + tf32 attention + scatter + bitmap.
// One CTA per head: 96 CTAs x 1024 threads (32 warps) -> 8 warps/SMSP.
// ---------------------------------------------------------------------------
#define PITCH  68
#define PPITCH 132

__global__ __launch_bounds__(1024, 1)
void fused_kernel(const float* __restrict__ q, const float* __restrict__ k,
                  const float* __restrict__ v, float* __restrict__ out) {
    extern __shared__ float sm[];
    unsigned* keys = reinterpret_cast<unsigned*>(sm);   // 16 KB, dead after select
    float* qs = sm;                          // 128 x PITCH (dead after GEMM1)
    float* ks = qs + 128 * PITCH;            // 128 x PITCH (dead after GEMM1)
    float* vs = ks + 128 * PITCH;            // 128 x PITCH
    float* ps = sm;                          // 128 x PPITCH alias over qs+ks

    __shared__ int      sidx[TOPK];
    __shared__ unsigned mask[128];
    __shared__ int      hist[256];
    __shared__ int      s_digit, s_need, s_n;

    const int bh   = blockIdx.x;
    const int tid  = threadIdx.x;
    const int lane = tid & 31;
    const int w    = tid >> 5;           // 32 warps

    // ---- Phase A: load keys, radix-select the 128th-largest --------------
    const unsigned* krow = g_key + (size_t)bh * S;
    for (int i = tid; i < S; i += 1024) keys[i] = krow[i];
    if (tid < 128) mask[tid] = 0u;

    unsigned prefix = 0u;
    int need = TOPK;

    #pragma unroll
    for (int shift = 24; shift >= 0; shift -= 8) {
        if (tid < 256) hist[tid] = 0;
        __syncthreads();

        unsigned pmask = (shift == 24) ? 0u : (0xFFFFFFFFu << (shift + 8));
        for (int i = tid; i < S; i += 1024) {
            unsigned u = keys[i];
            if ((u & pmask) == prefix)
                atomicAdd(&hist[(u >> shift) & 255u], 1);
        }
        __syncthreads();

        if (tid < 32) {
            int base = 255 - tid * 8;
            int h[8];
            int gs = 0;
            #pragma unroll
            for (int j = 0; j < 8; j++) { h[j] = hist[base - j]; gs += h[j]; }
            int pre = gs;
            #pragma unroll
            for (int o = 1; o < 32; o <<= 1) {
                int t = __shfl_up_sync(0xFFFFFFFFu, pre, o);
                if (tid >= o) pre += t;
            }
            int excl = pre - gs;
            if (excl < need && need <= pre) {
                int cum = excl, j = 0;
                #pragma unroll
                for (; j < 8; j++) { cum += h[j]; if (cum >= need) break; }
                s_digit = base - j;
                s_need  = need - (cum - h[j]);
            }
        }
        __syncthreads();
        prefix |= ((unsigned)s_digit) << shift;
        need = s_need;
        __syncthreads();
    }

    const unsigned T = prefix;

    if (tid == 0) s_n = 0;
    __syncthreads();
    for (int i = tid; i < S; i += 1024) {
        if (keys[i] > T) {
            int p = atomicAdd(&s_n, 1);
            sidx[p] = i;
        }
    }
    __syncthreads();
    for (int i = tid; i < S; i += 1024) {
        if (keys[i] == T) {
            int p = atomicAdd(&s_n, 1);
            if (p < TOPK) sidx[p] = i;
        }
    }
    __syncthreads();
    if (tid < TOPK)
        atomicOr(&mask[sidx[tid] >> 5], 1u << (sidx[tid] & 31));
    __syncthreads();
    if (tid < 128) g_selmask[bh * 128 + tid] = mask[tid];
    // (no extra sync needed: next phase writes over keys AFTER this barrier)

    const size_t base = (size_t)bh * S * D;

    // ---- Phase B: gather q,k,v (tf32-rounded) into smem ------------------
    // 8 threads per row, 2 float4 each per tensor.
    {
        int r = tid >> 3, p = tid & 7;
        size_t goff = base + (size_t)sidx[r] * D + p * 8;
        const float4* gq = reinterpret_cast<const float4*>(q + goff);
        const float4* gk = reinterpret_cast<const float4*>(k + goff);
        const float4* gv = reinterpret_cast<const float4*>(v + goff);
        float* dq = qs + r * PITCH + p * 8;
        float* dk = ks + r * PITCH + p * 8;
        float* dv = vs + r * PITCH + p * 8;
        #pragma unroll
        for (int i = 0; i < 2; i++) {
            float4 q4 = gq[i], k4 = gk[i], v4 = gv[i];
            q4.x = to_tf32(q4.x); q4.y = to_tf32(q4.y);
            q4.z = to_tf32(q4.z); q4.w = to_tf32(q4.w);
            k4.x = to_tf32(k4.x); k4.y = to_tf32(k4.y);
            k4.z = to_tf32(k4.z); k4.w = to_tf32(k4.w);
            v4.x = to_tf32(v4.x); v4.y = to_tf32(v4.y);
            v4.z = to_tf32(v4.z); v4.w = to_tf32(v4.w);
            reinterpret_cast<float4*>(dq)[i] = q4;
            reinterpret_cast<float4*>(dk)[i] = k4;
            reinterpret_cast<float4*>(dv)[i] = v4;
        }
    }
    __syncthreads();

    const int wm = w & 7;                // 8 m-groups of 16 rows
    const int wn = w >> 3;               // 4 n-groups
    const int m0 = wm * 16;
    const int lr = lane >> 2;
    const int lc = lane & 3;

    // ---- Phase C: GEMM1, warp tile 16x32 (4 nb), 8 k-steps ---------------
    float c1[4][4];
    #pragma unroll
    for (int nb = 0; nb < 4; nb++)
        #pragma unroll
        for (int j = 0; j < 4; j++) c1[nb][j] = 0.0f;

    #pragma unroll
    for (int kk = 0; kk < 8; kk++) {
        const int k0 = kk * 8;
        unsigned a0 = __float_as_uint(qs[(m0 + lr)     * PITCH + k0 + lc]);
        unsigned a1 = __float_as_uint(qs[(m0 + lr + 8) * PITCH + k0 + lc]);
        unsigned a2 = __float_as_uint(qs[(m0 + lr)     * PITCH + k0 + lc + 4]);
        unsigned a3 = __float_as_uint(qs[(m0 + lr + 8) * PITCH + k0 + lc + 4]);
        #pragma unroll
        for (int nb = 0; nb < 4; nb++) {
            const int n0 = wn * 32 + nb * 8;
            unsigned b0 = __float_as_uint(ks[(n0 + lr) * PITCH + k0 + lc]);
            unsigned b1 = __float_as_uint(ks[(n0 + lr) * PITCH + k0 + lc + 4]);
            mma_tf32(c1[nb], a0, a1, a2, a3, b0, b1);
        }
    }
    __syncthreads();   // all warps done reading qs/ks before ps overwrite

    #pragma unroll
    for (int nb = 0; nb < 4; nb++) {
        const int col = wn * 32 + nb * 8 + lc * 2;
        ps[(m0 + lr)     * PPITCH + col]     = c1[nb][0] * 0.125f;
        ps[(m0 + lr)     * PPITCH + col + 1] = c1[nb][1] * 0.125f;
        ps[(m0 + lr + 8) * PPITCH + col]     = c1[nb][2] * 0.125f;
        ps[(m0 + lr + 8) * PPITCH + col + 1] = c1[nb][3] * 0.125f;
    }
    __syncthreads();

    // ---- Phase D: row softmax (32 warps x 4 rows), tf32 probs ------------
    #pragma unroll
    for (int rr = 0; rr < 4; rr++) {
        int r = w * 4 + rr;
        float* row = ps + r * PPITCH;
        float x[4];
        float mx = -1e30f;
        #pragma unroll
        for (int c = 0; c < 4; c++) { x[c] = row[lane + 32 * c]; mx = fmaxf(mx, x[c]); }
        #pragma unroll
        for (int o = 16; o; o >>= 1) mx = fmaxf(mx, __shfl_xor_sync(0xFFFFFFFFu, mx, o));
        float ssum = 0.0f;
        #pragma unroll
        for (int c = 0; c < 4; c++) { x[c] = __expf(x[c] - mx); ssum += x[c]; }
        #pragma unroll
        for (int o = 16; o; o >>= 1) ssum += __shfl_xor_sync(0xFFFFFFFFu, ssum, o);
        float inv = 1.0f / ssum;
        #pragma unroll
        for (int c = 0; c < 4; c++) row[lane + 32 * c] = to_tf32(x[c] * inv);
    }
    __syncthreads();

    // ---- Phase E: GEMM2, warp tile 16x16 (2 nb), 16 k-steps + scatter ----
    float c2[2][4];
    #pragma unroll
    for (int nb = 0; nb < 2; nb++)
        #pragma unroll
        for (int j = 0; j < 4; j++) c2[nb][j] = 0.0f;

    #pragma unroll
    for (int kk = 0; kk < 16; kk++) {
        const int k0 = kk * 8;
        unsigned a0 = __float_as_uint(ps[(m0 + lr)     * PPITCH + k0 + lc]);
        unsigned a1 = __float_as_uint(ps[(m0 + lr + 8) * PPITCH + k0 + lc]);
        unsigned a2 = __float_as_uint(ps[(m0 + lr)     * PPITCH + k0 + lc + 4]);
        unsigned a3 = __float_as_uint(ps[(m0 + lr + 8) * PPITCH + k0 + lc + 4]);
        #pragma unroll
        for (int nb = 0; nb < 2; nb++) {
            const int n0 = wn * 16 + nb * 8;
            unsigned b0 = __float_as_uint(vs[(k0 + lc)     * PITCH + n0 + lr]);
            unsigned b1 = __float_as_uint(vs[(k0 + lc + 4) * PITCH + n0 + lr]);
            mma_tf32(c2[nb], a0, a1, a2, a3, b0, b1);
        }
    }

    {
        int r0g = sidx[m0 + lr];
        int r1g = sidx[m0 + lr + 8];
        float* o0 = out + base + (size_t)r0g * D;
        float* o1 = out + base + (size_t)r1g * D;
        #pragma unroll
        for (int nb = 0; nb < 2; nb++) {
            const int d0 = wn * 16 + nb * 8 + lc * 2;
            *reinterpret_cast<float2*>(o0 + d0) = make_float2(c2[nb][0], c2[nb][1]);
            *reinterpret_cast<float2*>(o1 + d0) = make_float2(c2[nb][2], c2[nb][3]);
        }
    }
}

// ---------------------------------------------------------------------------
// Kernel 3: zero all UNSELECTED output rows. WIDE grid (1536 CTAs) for full
// write bandwidth. Runs after attn; rows are disjoint from attn's writes.
// ---------------------------------------------------------------------------
__global__ __launch_bounds__(256)
void zero_kernel(float* __restrict__ out) {
    __shared__ unsigned mask[8];
    const int bh  = blockIdx.x >> 4;
    const int seg = blockIdx.x & 15;          // 256 rows per segment
    const int tid = threadIdx.x;
    if (tid < 8) mask[tid] = g_selmask[bh * 128 + seg * 8 + tid];
    __syncthreads();

    float4* obase = reinterpret_cast<float4*>(out + (size_t)bh * S * D) + (seg * 256) * 16;
    const float4 z = make_float4(0.f, 0.f, 0.f, 0.f);

    // 256 rows x 16 float4 = 4096 float4; 16 per thread
    #pragma unroll 4
    for (int i = tid; i < 256 * 16; i += 256) {
        int r = i >> 4;
        if (!(mask[r >> 5] & (1u << (r & 31))))
            obase[i] = z;
    }
}

// ---------------------------------------------------------------------------
extern "C" void kernel_launch(void* const* d_in, const int* in_sizes, int n_in,
                              void* d_out, int out_size) {
    const float* q = (const float*)d_in[0];
    const float* k = (const float*)d_in[1];
    const float* v = (const float*)d_in[2];
    float* out = (float*)d_out;

    const int fused_smem = (3 * 128 * PITCH) * (int)sizeof(float);
    cudaFuncSetAttribute(fused_kernel, cudaFuncAttributeMaxDynamicSharedMemorySize,
                         fused_smem);

    // 1) importance keys (wide grid)
    imp_kernel<<<(BH * S) / 128, 256>>>(q);

    // 2) fused select + tensor-core attention (1 CTA/head, 1024 threads)
    fused_kernel<<<BH, 1024, fused_smem>>>(q, k, v, out);

    // 3) zero unselected rows (wide grid, full write bandwidth)
    zero_kernel<<<BH * 16, 256>>>(out);
}